// round 16
// baseline (speedup 1.0000x reference)
#include <cuda_runtime.h>
#include <cuda_fp16.h>

#define NN 50000
#define NE 50000
#define NI 3125
#define F 128
#define S1 152      // edge A stride (K=144 used)
#define SN 136      // node A stride (K=128)
#define SPI 136     // pi A stride (K=128)
#define KE 144      // edge layer-1 K (h_j 128 + eattr 16; r in FMA init)
#define KH 128      // node Wh1 K (m_i row in FMA init)

// weights stored in mma B-fragment order:
// o = ((c*8 + jj)*32 + lane)*8 + q ; j = jj*2 + (q>>2), fi = q&3
// k = c*16 + (lane&3)*2 + (fi&1) + ((fi&2)?8:0) ; n = j*8 + (lane>>2)
__device__ __align__(16) __half g_Wpi[F*F];
__device__ __align__(16) __half g_W1[KE*F];
__device__ __align__(16) __half g_W2[F*F];
__device__ __align__(16) __half g_Wx[F*F];
__device__ __align__(16) __half g_Wv[F*F];
__device__ __align__(16) __half g_Wh1[KH*F];
__device__ __align__(16) __half g_Wh2[F*F];
__device__ float g_Pi[NI * F];
__device__ float2 g_sMA[NN];                     // .x = sM, .y = sA

__device__ __forceinline__ float ftanh(float v) {
    float r; asm("tanh.approx.f32 %0, %1;" : "=f"(r) : "f"(v)); return r;
}
__device__ __forceinline__ float4 ldg4(const float* p) {
    return __ldg(reinterpret_cast<const float4*>(p));
}
__device__ __forceinline__ float2 ldg2(const float* p) {
    return __ldg(reinterpret_cast<const float2*>(p));
}
__device__ __forceinline__ unsigned s2u(const void* p) {
    return (unsigned)__cvta_generic_to_shared(p);
}
__device__ __forceinline__ void ldsm4(unsigned a, unsigned* r) {
    asm volatile("ldmatrix.sync.aligned.m8n8.x4.shared.b16 {%0,%1,%2,%3}, [%4];"
                 : "=r"(r[0]), "=r"(r[1]), "=r"(r[2]), "=r"(r[3]) : "r"(a));
}
__device__ __forceinline__ void mma16816(float* c, const unsigned a[4],
                                         unsigned b0, unsigned b1) {
    asm volatile("mma.sync.aligned.m16n8k16.row.col.f32.f16.f16.f32 "
                 "{%0,%1,%2,%3}, {%4,%5,%6,%7}, {%8,%9}, {%0,%1,%2,%3};"
                 : "+f"(c[0]), "+f"(c[1]), "+f"(c[2]), "+f"(c[3])
                 : "r"(a[0]), "r"(a[1]), "r"(a[2]), "r"(a[3]), "r"(b0), "r"(b1));
}
__device__ __forceinline__ unsigned h2u(__half a, __half b) {
    __half2 h = __halves2half2(a, b);
    return *reinterpret_cast<unsigned*>(&h);
}
__device__ __forceinline__ void split8(float4 v0, float4 v1, uint4& hi, uint4& lo) {
    __half h0 = __float2half_rn(v0.x), h1 = __float2half_rn(v0.y);
    __half h2 = __float2half_rn(v0.z), h3 = __float2half_rn(v0.w);
    __half h4 = __float2half_rn(v1.x), h5 = __float2half_rn(v1.y);
    __half h6 = __float2half_rn(v1.z), h7 = __float2half_rn(v1.w);
    hi.x = h2u(h0, h1); hi.y = h2u(h2, h3); hi.z = h2u(h4, h5); hi.w = h2u(h6, h7);
    lo.x = h2u(__float2half_rn(v0.x - __half2float(h0)),
               __float2half_rn(v0.y - __half2float(h1)));
    lo.y = h2u(__float2half_rn(v0.z - __half2float(h2)),
               __float2half_rn(v0.w - __half2float(h3)));
    lo.z = h2u(__float2half_rn(v1.x - __half2float(h4)),
               __float2half_rn(v1.y - __half2float(h5)));
    lo.w = h2u(__float2half_rn(v1.z - __half2float(h6)),
               __float2half_rn(v1.w - __half2float(h7)));
}
__device__ __forceinline__ void st_hi(__half* ph, float a, float b) {
    *reinterpret_cast<half2*>(ph) =
        __halves2half2(__float2half_rn(a), __float2half_rn(b));
}

// D[NWM*32][128] += A @ B.  NW warps: NWM m-strips x 2 n-halves (m32n64).
// B read directly from global in fragment order (one LDG.128 per n16 tile).
template <int NCH, int SAW, bool LO, int NW>
__device__ void run_layer(const __half* Ah, const __half* Al,
                          const __half* __restrict__ gBf,
                          float acc[16][4], int tid) {
    constexpr int NWM = NW / 2;
    const int lane = tid & 31, wid = tid >> 5;
    const int s = wid & (NWM - 1), nh = wid / NWM;
    const int alr = lane & 15, ac8 = (lane >> 4) << 3;

    __syncthreads();   // A written by all warps -> visible
#pragma unroll
    for (int c = 0; c < NCH; c++) {
        uint4 bfr[4];
#pragma unroll
        for (int nn = 0; nn < 4; nn++)
            bfr[nn] = __ldg(reinterpret_cast<const uint4*>(
                gBf + ((size_t)(c * 8 + nh * 4 + nn) * 32 + lane) * 8));
        unsigned ah[2][4], al[2][4];
#pragma unroll
        for (int m = 0; m < 2; m++) {
            ldsm4(s2u(Ah + (s * 32 + m * 16 + alr) * SAW + c * 16 + ac8), ah[m]);
            if (LO)
                ldsm4(s2u(Al + (s * 32 + m * 16 + alr) * SAW + c * 16 + ac8), al[m]);
        }
#pragma unroll
        for (int nn = 0; nn < 4; nn++) {
#pragma unroll
            for (int m = 0; m < 2; m++) {
                float* c0 = acc[m * 8 + nn * 2];
                float* c1 = acc[m * 8 + nn * 2 + 1];
                mma16816(c0, ah[m], bfr[nn].x, bfr[nn].y);
                if (LO) mma16816(c0, al[m], bfr[nn].x, bfr[nn].y);
                mma16816(c1, ah[m], bfr[nn].z, bfr[nn].w);
                if (LO) mma16816(c1, al[m], bfr[nn].z, bfr[nn].w);
            }
        }
    }
    __syncthreads();   // all warps done reading A -> epilogue may overwrite
}

#define INIT_BIAS16(bp)                                                   \
    { _Pragma("unroll") for (int p = 0; p < 16; p++) {                    \
        int col = nh * 64 + (p & 7) * 8 + 2 * t;                          \
        float b0 = __ldg((bp) + col), b1 = __ldg((bp) + col + 1);         \
        acc[p][0] = b0; acc[p][1] = b1; acc[p][2] = b0; acc[p][3] = b1; } }

__device__ __forceinline__ void reduce_rows16(float acc[16][4], const float* w,
                                              float* red, int s, int nh,
                                              int g, int t) {
    float ra[2] = {0.f, 0.f}, rb[2] = {0.f, 0.f};
#pragma unroll
    for (int p = 0; p < 16; p++) {
        int m = p >> 3, col = nh * 64 + (p & 7) * 8 + 2 * t;
        float w0 = w ? __ldg(w + col) : 1.f;
        float w1 = w ? __ldg(w + col + 1) : 1.f;
        ra[m] += ftanh(acc[p][0]) * w0 + ftanh(acc[p][1]) * w1;
        rb[m] += ftanh(acc[p][2]) * w0 + ftanh(acc[p][3]) * w1;
    }
#pragma unroll
    for (int m = 0; m < 2; m++) {
        ra[m] += __shfl_xor_sync(~0u, ra[m], 1); ra[m] += __shfl_xor_sync(~0u, ra[m], 2);
        rb[m] += __shfl_xor_sync(~0u, rb[m], 1); rb[m] += __shfl_xor_sync(~0u, rb[m], 2);
        if (t == 0) {
            red[(s * 32 + m * 16 + g) * 2 + nh] = ra[m];
            red[(s * 32 + m * 16 + 8 + g) * 2 + nh] = rb[m];
        }
    }
}

// fragment-order (k,n) decode
__device__ __forceinline__ void fragkn(int o, int& k, int& n) {
    int q = o & 7, lane = (o >> 3) & 31, jj = (o >> 8) & 7, c = o >> 11;
    int j = jj * 2 + (q >> 2), fi = q & 3;
    k = c * 16 + (lane & 3) * 2 + (fi & 1) + ((fi & 2) ? 8 : 0);
    n = j * 8 + (lane >> 2);
}

__global__ __launch_bounds__(256) void prep_kernel(
        const float* __restrict__ We1, const float* __restrict__ We2,
        const float* __restrict__ Wx1, const float* __restrict__ Wv1,
        const float* __restrict__ Wh1, const float* __restrict__ Wh2) {
    int o = blockIdx.x * 256 + threadIdx.x;
    float v; __half* dst; int idx, k, n;
    if (o < F * F) {
        idx = o; dst = g_Wpi; fragkn(o, k, n); v = __ldg(We1 + k * F + n);
    } else if ((o -= F * F) < KE * F) {
        idx = o; dst = g_W1; fragkn(o, k, n);
        int src = (k < 128) ? (128 + k) : (129 + k);   // skip row 256 (r)
        v = __ldg(We1 + src * F + n);
    } else if ((o -= KE * F) < F * F) {
        idx = o; dst = g_W2; fragkn(o, k, n); v = __ldg(We2 + k * F + n);
    } else if ((o -= F * F) < F * F) {
        idx = o; dst = g_Wx; fragkn(o, k, n); v = __ldg(Wx1 + k * F + n);
    } else if ((o -= F * F) < F * F) {
        idx = o; dst = g_Wv; fragkn(o, k, n); v = __ldg(Wv1 + k * F + n);
    } else if ((o -= F * F) < KH * F) {
        idx = o; dst = g_Wh1; fragkn(o, k, n); v = __ldg(Wh1 + k * F + n);
    } else if ((o -= KH * F) < F * F) {
        idx = o; dst = g_Wh2; fragkn(o, k, n); v = __ldg(Wh2 + k * F + n);
    } else return;
    dst[idx] = __float2half_rn(v);
}

// ---------------- pi kernel: Pi = h[0:3125] @ We1[0:128] + be1 -------------
__global__ __launch_bounds__(256, 2) void pi_kernel(const float* __restrict__ h,
                                                    const float* __restrict__ be1) {
    extern __shared__ __align__(16) char smraw[];
    __half* Ah = (__half*)smraw;
    __half* Al = Ah + 128 * SPI;

    int tid = threadIdx.x, lane = tid & 31, wid = tid >> 5;
    int s = wid & 3, nh = wid >> 2, g = lane >> 2, t = lane & 3;
    int i0 = blockIdx.x * 128;

    {
        int e = tid >> 1, q = tid & 1;
        int i = i0 + e; if (i >= NI) i = NI - 1;
        const float* ph = h + (size_t)i * F + q * 64;
#pragma unroll
        for (int u = 0; u < 8; u++) {
            float4 v0 = ldg4(ph + u * 8), v1 = ldg4(ph + u * 8 + 4);
            uint4 hi, lo; split8(v0, v1, hi, lo);
            *reinterpret_cast<uint4*>(Ah + e * SPI + q * 64 + u * 8) = hi;
            *reinterpret_cast<uint4*>(Al + e * SPI + q * 64 + u * 8) = lo;
        }
    }
    float acc[16][4];
    INIT_BIAS16(be1);
    run_layer<8, SPI, true, 8>(Ah, Al, g_Wpi, acc, tid);
#pragma unroll
    for (int p = 0; p < 16; p++) {
        int m = p >> 3, col = nh * 64 + (p & 7) * 8 + 2 * t;
        int r0 = s * 32 + m * 16 + g, r1 = r0 + 8;
        if (i0 + r0 < NI)
            *reinterpret_cast<float2*>(&g_Pi[(i0 + r0) * F + col]) =
                make_float2(acc[p][0], acc[p][1]);
        if (i0 + r1 < NI)
            *reinterpret_cast<float2*>(&g_Pi[(i0 + r1) * F + col]) =
                make_float2(acc[p][2], acc[p][3]);
    }
}

// ------------- edge kernel: 64 edges/block, 128 threads, 4 blk/SM ---------
__global__ __launch_bounds__(128, 4) void edge_kernel(
        const float* __restrict__ h, const float* __restrict__ x,
        const float* __restrict__ eattr, const int* __restrict__ cols,
        const float* __restrict__ We1, const float* __restrict__ be2,
        const float* __restrict__ bx1, const float* __restrict__ Wx2,
        const float* __restrict__ bx2) {
    extern __shared__ __align__(16) char smraw[];
    __half* Ah = (__half*)smraw;            // [64][S1]
    __half* Al = Ah + 64 * S1;
    float* red  = (float*)(Al + 64 * S1);       // [64][2]
    float* sumd = red + 128;                    // [64]
    float* rr   = sumd + 64;                    // [64]
    int*   cs   = (int*)(rr + 64);              // [64]

    int tid = threadIdx.x, lane = tid & 31, wid = tid >> 5;
    int s = wid & 1, nh = wid >> 1, g = lane >> 2, t = lane & 3;
    int j0 = blockIdx.x * 64;

    if (tid < 64) {
        int j = j0 + tid; if (j >= NE) j = NE - 1;
        int c = __ldg(cols + j);
        cs[tid] = c;
        int i = j >> 4;
        float dx = x[i * 3 + 0] - x[c * 3 + 0];
        float dy = x[i * 3 + 1] - x[c * 3 + 1];
        float dz = x[i * 3 + 2] - x[c * 3 + 2];
        sumd[tid] = dx + dy + dz;
        rr[tid] = dx * dx + dy * dy + dz * dz;
        const float* pe = eattr + (size_t)j * 16;
        float4 a0 = ldg4(pe), a1 = ldg4(pe + 4), a2 = ldg4(pe + 8), a3 = ldg4(pe + 12);
        uint4 hi, lo;
        split8(a0, a1, hi, lo);
        *reinterpret_cast<uint4*>(Ah + tid * S1 + 128) = hi;
        *reinterpret_cast<uint4*>(Al + tid * S1 + 128) = lo;
        split8(a2, a3, hi, lo);
        *reinterpret_cast<uint4*>(Ah + tid * S1 + 136) = hi;
        *reinterpret_cast<uint4*>(Al + tid * S1 + 136) = lo;
    }
    __syncthreads();
    {   // gather h_j into cols 0..127 (2 threads per row)
        int e = tid >> 1, q = tid & 1;
        const float* pj = h + (size_t)cs[e] * F + q * 64;
#pragma unroll
        for (int u = 0; u < 8; u++) {
            float4 v0 = ldg4(pj + u * 8), v1 = ldg4(pj + u * 8 + 4);
            uint4 hi, lo; split8(v0, v1, hi, lo);
            *reinterpret_cast<uint4*>(Ah + e * S1 + q * 64 + u * 8) = hi;
            *reinterpret_cast<uint4*>(Al + e * S1 + q * 64 + u * 8) = lo;
        }
    }
    float acc[16][4];

    // layer 1 (compensated): acc = Pi + r * We1[256]
    {
        const float* Wr = We1 + 256 * F;
#pragma unroll
        for (int p = 0; p < 16; p++) {
            int m = p >> 3;
            int iPi = j0 / 16 + 2 * s + m;
            if (iPi >= NI) iPi = NI - 1;
            int col = nh * 64 + (p & 7) * 8 + 2 * t;
            int r0 = s * 32 + m * 16 + g, r1 = r0 + 8;
            float2 pv = *reinterpret_cast<const float2*>(&g_Pi[iPi * F + col]);
            float2 w = ldg2(Wr + col);
            acc[p][0] = fmaf(rr[r0], w.x, pv.x);
            acc[p][1] = fmaf(rr[r0], w.y, pv.y);
            acc[p][2] = fmaf(rr[r1], w.x, pv.x);
            acc[p][3] = fmaf(rr[r1], w.y, pv.y);
        }
    }
    run_layer<KE / 16, S1, true, 4>(Ah, Al, g_W1, acc, tid);
#pragma unroll
    for (int p = 0; p < 16; p++) {   // t1 stored hi-only
        int m = p >> 3, col = nh * 64 + (p & 7) * 8 + 2 * t;
        int r0 = s * 32 + m * 16 + g, r1 = r0 + 8;
        st_hi(Ah + r0 * S1 + col, ftanh(acc[p][0]), ftanh(acc[p][1]));
        st_hi(Ah + r1 * S1 + col, ftanh(acc[p][2]), ftanh(acc[p][3]));
    }
    // layer 2: m = tanh(t1 @ We2 + be2); sM
    INIT_BIAS16(be2);
    run_layer<8, S1, false, 4>(Ah, Al, g_W2, acc, tid);
    {
        float ra[2] = {0.f, 0.f}, rb[2] = {0.f, 0.f};
#pragma unroll
        for (int p = 0; p < 16; p++) {
            int m = p >> 3, col = nh * 64 + (p & 7) * 8 + 2 * t;
            int r0 = s * 32 + m * 16 + g, r1 = r0 + 8;
            float m0 = ftanh(acc[p][0]), m1 = ftanh(acc[p][1]);
            float m2 = ftanh(acc[p][2]), m3 = ftanh(acc[p][3]);
            st_hi(Ah + r0 * S1 + col, m0, m1);
            st_hi(Ah + r1 * S1 + col, m2, m3);
            ra[m] += m0 + m1; rb[m] += m2 + m3;
        }
#pragma unroll
        for (int m = 0; m < 2; m++) {
            ra[m] += __shfl_xor_sync(~0u, ra[m], 1); ra[m] += __shfl_xor_sync(~0u, ra[m], 2);
            rb[m] += __shfl_xor_sync(~0u, rb[m], 1); rb[m] += __shfl_xor_sync(~0u, rb[m], 2);
            if (t == 0) {
                red[(s * 32 + m * 16 + g) * 2 + nh] = ra[m];
                red[(s * 32 + m * 16 + 8 + g) * 2 + nh] = rb[m];
            }
        }
    }
    __syncthreads();
    if (tid < 64) {
        int j = j0 + tid;
        if (j < NE)
            ((float*)g_sMA)[2 * j] = red[tid * 2] + red[tid * 2 + 1];
    }
    // layer 3: u = tanh(m@Wx1+bx1); phi = tanh(u.Wx2+bx2); sA
    INIT_BIAS16(bx1);
    run_layer<8, S1, false, 4>(Ah, Al, g_Wx, acc, tid);
    reduce_rows16(acc, Wx2, red, s, nh, g, t);
    __syncthreads();
    if (tid < 64) {
        int j = j0 + tid;
        if (j < NE) {
            float phi = ftanh(red[tid * 2] + red[tid * 2 + 1] + __ldg(bx2));
            ((float*)g_sMA)[2 * j + 1] = phi * sumd[tid];
        }
    }
}

// ---------------- node kernel: 64 nodes/block, 128 threads, 4 blk/SM ------
__global__ __launch_bounds__(128, 4) void node_kernel(
        const float* __restrict__ h, const float* __restrict__ x,
        const float* __restrict__ vel, const int* __restrict__ cols,
        const float* __restrict__ bv1, const float* __restrict__ Wv2,
        const float* __restrict__ bv2, const float* __restrict__ Wh1,
        const float* __restrict__ bh1, const float* __restrict__ bh2,
        float* __restrict__ out_h, float* __restrict__ out_x,
        float* __restrict__ out_v) {
    extern __shared__ __align__(16) char smraw[];
    __half* Ah = (__half*)smraw;            // [64][SN]
    __half* Al = Ah + 64 * SN;
    float* red  = (float*)(Al + 64 * SN);       // [64][2]
    float* meds = red + 128;                    // [64]
    float* pvs  = meds + 64;                    // [64]
    float* mis  = pvs + 64;                     // [64]

    int tid = threadIdx.x, lane = tid & 31, wid = tid >> 5;
    int s = wid & 1, nh = wid >> 1, g = lane >> 2, t = lane & 3;
    int i0 = blockIdx.x * 64;

    {
        int e = tid >> 1, q = tid & 1;
        int i = i0 + e;
        int is = (i < NN) ? i : 0;
        const float* ph = h + (size_t)is * F + q * 64;
#pragma unroll
        for (int u = 0; u < 8; u++) {
            float4 v0 = ldg4(ph + u * 8), v1 = ldg4(ph + u * 8 + 4);
            uint4 hi, lo; split8(v0, v1, hi, lo);
            *reinterpret_cast<uint4*>(Ah + e * SN + q * 64 + u * 8) = hi;
            *reinterpret_cast<uint4*>(Al + e * SN + q * 64 + u * 8) = lo;
        }
        float sm = 0.f, sa = 0.f;
#pragma unroll
        for (int u = 0; u < 8; u++) {
            int c = __ldg(cols + (size_t)is * 16 + q * 8 + u);
            float2 v = __ldg(&g_sMA[c]);
            sm += v.x; sa += v.y;
        }
        sm += __shfl_xor_sync(~0u, sm, 1);
        sa += __shfl_xor_sync(~0u, sa, 1);
        if (q == 0) { meds[e] = sa * (1.f / 16.f); mis[e] = sm; }
    }
    float acc[16][4];

    // phi_v (A hi-only) = tanh(h@Wv1+bv1).Wv2 + bv2
    INIT_BIAS16(bv1);
    run_layer<8, SN, false, 4>(Ah, Al, g_Wv, acc, tid);
    reduce_rows16(acc, Wv2, red, s, nh, g, t);
    __syncthreads();
    if (tid < 64) pvs[tid] = red[tid * 2] + red[tid * 2 + 1] + __ldg(bv2);

    // t2 (compensated) = tanh(h @ Wh1[0:128] + m_i*Wh1[128] + bh1)
    {
        const float* W128 = Wh1 + 128 * F;
#pragma unroll
        for (int p = 0; p < 16; p++) {
            int m = p >> 3, col = nh * 64 + (p & 7) * 8 + 2 * t;
            int r0 = s * 32 + m * 16 + g, r1 = r0 + 8;
            float2 b = ldg2(bh1 + col);
            float2 w = ldg2(W128 + col);
            acc[p][0] = fmaf(mis[r0], w.x, b.x);
            acc[p][1] = fmaf(mis[r0], w.y, b.y);
            acc[p][2] = fmaf(mis[r1], w.x, b.x);
            acc[p][3] = fmaf(mis[r1], w.y, b.y);
        }
    }
    run_layer<8, SN, true, 4>(Ah, Al, g_Wh1, acc, tid);
#pragma unroll
    for (int p = 0; p < 16; p++) {
        int m = p >> 3, col = nh * 64 + (p & 7) * 8 + 2 * t;
        int r0 = s * 32 + m * 16 + g, r1 = r0 + 8;
        st_hi(Ah + r0 * SN + col, ftanh(acc[p][0]), ftanh(acc[p][1]));
        st_hi(Ah + r1 * SN + col, ftanh(acc[p][2]), ftanh(acc[p][3]));
    }
    // h_new (uncompensated A) = t2 @ Wh2 + bh2
    INIT_BIAS16(bh2);
    run_layer<8, SN, false, 4>(Ah, Al, g_Wh2, acc, tid);
#pragma unroll
    for (int p = 0; p < 16; p++) {
        int m = p >> 3, col = nh * 64 + (p & 7) * 8 + 2 * t;
        int r0 = s * 32 + m * 16 + g, r1 = r0 + 8;
        int ia = i0 + r0, ib = i0 + r1;
        if (ia < NN)
            *reinterpret_cast<float2*>(&out_h[(size_t)ia * F + col]) =
                make_float2(acc[p][0], acc[p][1]);
        if (ib < NN)
            *reinterpret_cast<float2*>(&out_h[(size_t)ib * F + col]) =
                make_float2(acc[p][2], acc[p][3]);
    }
    if (tid < 64) {
        int i = i0 + tid;
        if (i < NN) {
            float pv = pvs[tid], med = meds[tid];
#pragma unroll
            for (int d = 0; d < 3; d++) {
                float v = vel[i * 3 + d] * pv + med;
                out_v[i * 3 + d] = v;
                out_x[i * 3 + d] = x[i * 3 + d] + v;
            }
        }
    }
}

extern "C" void kernel_launch(void* const* d_in, const int* in_sizes, int n_in,
                              void* d_out, int out_size) {
    const float* h     = (const float*)d_in[0];
    const float* x     = (const float*)d_in[1];
    const float* vel   = (const float*)d_in[2];
    const float* eattr = (const float*)d_in[3];
    const int*   cols  = (const int*)d_in[5];
    const float* We1 = (const float*)d_in[6];
    const float* be1 = (const float*)d_in[7];
    const float* We2 = (const float*)d_in[8];
    const float* be2 = (const float*)d_in[9];
    const float* Wx1 = (const float*)d_in[10];
    const float* bx1 = (const float*)d_in[11];
    const float* Wx2 = (const float*)d_in[12];
    const float* bx2 = (const float*)d_in[13];
    const float* Wh1 = (const float*)d_in[14];
    const float* bh1 = (const float*)d_in[15];
    const float* Wh2 = (const float*)d_in[16];
    const float* bh2 = (const float*)d_in[17];
    const float* Wv1 = (const float*)d_in[18];
    const float* bv1 = (const float*)d_in[19];
    const float* Wv2 = (const float*)d_in[20];
    const float* bv2 = (const float*)d_in[21];

    float* out   = (float*)d_out;
    float* out_h = out;
    float* out_x = out + (size_t)NN * F;
    float* out_v = out_x + (size_t)NN * 3;

    int smem_pi   = 2 * 128 * SPI * 2;
    int smem_edge = 2 * 64 * S1 * 2 + (128 + 64 + 64 + 64) * 4;
    int smem_node = 2 * 64 * SN * 2 + (128 + 64 + 64 + 64) * 4;
    cudaFuncSetAttribute((const void*)pi_kernel,
                         cudaFuncAttributeMaxDynamicSharedMemorySize, smem_pi);
    cudaFuncSetAttribute((const void*)edge_kernel,
                         cudaFuncAttributeMaxDynamicSharedMemorySize, smem_edge);
    cudaFuncSetAttribute((const void*)node_kernel,
                         cudaFuncAttributeMaxDynamicSharedMemorySize, smem_node);

    int prep_elems = 5 * F * F + KE * F + KH * F;
    prep_kernel<<<(prep_elems + 255) / 256, 256>>>(We1, We2, Wx1, Wv1, Wh1, Wh2);
    pi_kernel<<<(NI + 127) / 128, 256, smem_pi>>>(h, be1);
    edge_kernel<<<(NE + 63) / 64, 128, smem_edge>>>(
        h, x, eattr, cols, We1, be2, bx1, Wx2, bx2);
    node_kernel<<<(NN + 63) / 64, 128, smem_node>>>(
        h, x, vel, cols, bv1, Wv2, bv2, Wh1, bh1, bh2, out_h, out_x, out_v);
}

// round 17
// speedup vs baseline: 1.1332x; 1.1332x over previous
#include <cuda_runtime.h>
#include <cuda_fp16.h>

#define NN 50000
#define NE 50000
#define NI 3125
#define F 128
#define S1 152      // edge A stride (K=144 used)
#define SN 136      // node A stride (K=128)
#define SPI 136     // pi A stride (K=128)
#define KE 144      // edge layer-1 K (h_j 128 + eattr 16; r in FMA init)
#define KH 128      // node Wh1 K (m_i row in FMA init)

// weights stored in mma B-fragment order:
// o = ((c*8 + jj)*32 + lane)*8 + q ; j = jj*2 + (q>>2), fi = q&3
// k = c*16 + (lane&3)*2 + (fi&1) + ((fi&2)?8:0) ; n = j*8 + (lane>>2)
__device__ __align__(16) __half g_Wpi[F*F];
__device__ __align__(16) __half g_W1[KE*F];
__device__ __align__(16) __half g_W2[F*F];
__device__ __align__(16) __half g_Wx[F*F];
__device__ __align__(16) __half g_Wv[F*F];
__device__ __align__(16) __half g_Wh1[KH*F];
__device__ __align__(16) __half g_Wh2[F*F];
__device__ float g_Pi[NI * F];
__device__ float2 g_sMA[NN];                     // .x = sM, .y = sA

__device__ __forceinline__ float ftanh(float v) {
    float r; asm("tanh.approx.f32 %0, %1;" : "=f"(r) : "f"(v)); return r;
}
__device__ __forceinline__ float4 ldg4(const float* p) {
    return __ldg(reinterpret_cast<const float4*>(p));
}
__device__ __forceinline__ float2 ldg2(const float* p) {
    return __ldg(reinterpret_cast<const float2*>(p));
}
__device__ __forceinline__ unsigned s2u(const void* p) {
    return (unsigned)__cvta_generic_to_shared(p);
}
__device__ __forceinline__ void ldsm4(unsigned a, unsigned* r) {
    asm volatile("ldmatrix.sync.aligned.m8n8.x4.shared.b16 {%0,%1,%2,%3}, [%4];"
                 : "=r"(r[0]), "=r"(r[1]), "=r"(r[2]), "=r"(r[3]) : "r"(a));
}
__device__ __forceinline__ void mma16816(float* c, const unsigned a[4],
                                         unsigned b0, unsigned b1) {
    asm volatile("mma.sync.aligned.m16n8k16.row.col.f32.f16.f16.f32 "
                 "{%0,%1,%2,%3}, {%4,%5,%6,%7}, {%8,%9}, {%0,%1,%2,%3};"
                 : "+f"(c[0]), "+f"(c[1]), "+f"(c[2]), "+f"(c[3])
                 : "r"(a[0]), "r"(a[1]), "r"(a[2]), "r"(a[3]), "r"(b0), "r"(b1));
}
__device__ __forceinline__ unsigned h2u(__half a, __half b) {
    __half2 h = __halves2half2(a, b);
    return *reinterpret_cast<unsigned*>(&h);
}
// convert 8 consecutive floats to fp16 uint4 (one STS.128)
__device__ __forceinline__ uint4 cvt8(float4 v0, float4 v1) {
    uint4 hi;
    hi.x = h2u(__float2half_rn(v0.x), __float2half_rn(v0.y));
    hi.y = h2u(__float2half_rn(v0.z), __float2half_rn(v0.w));
    hi.z = h2u(__float2half_rn(v1.x), __float2half_rn(v1.y));
    hi.w = h2u(__float2half_rn(v1.z), __float2half_rn(v1.w));
    return hi;
}
__device__ __forceinline__ void st_hi(__half* ph, float a, float b) {
    *reinterpret_cast<half2*>(ph) =
        __halves2half2(__float2half_rn(a), __float2half_rn(b));
}

// D[NWM*32][128] += A @ B.  NW warps: NWM m-strips x 2 n-halves (m32n64).
// A pure fp16 in smem; B read directly from global in fragment order
// (one LDG.128 per n16 tile). No staging, no per-chunk barriers.
template <int NCH, int SAW, int NW>
__device__ void run_layer(const __half* Ah,
                          const __half* __restrict__ gBf,
                          float acc[16][4], int tid) {
    constexpr int NWM = NW / 2;
    const int lane = tid & 31, wid = tid >> 5;
    const int s = wid & (NWM - 1), nh = wid / NWM;
    const int alr = lane & 15, ac8 = (lane >> 4) << 3;

    __syncthreads();   // A written by all warps -> visible
#pragma unroll
    for (int c = 0; c < NCH; c++) {
        uint4 bfr[4];
#pragma unroll
        for (int nn = 0; nn < 4; nn++)
            bfr[nn] = __ldg(reinterpret_cast<const uint4*>(
                gBf + ((size_t)(c * 8 + nh * 4 + nn) * 32 + lane) * 8));
        unsigned ah[2][4];
#pragma unroll
        for (int m = 0; m < 2; m++)
            ldsm4(s2u(Ah + (s * 32 + m * 16 + alr) * SAW + c * 16 + ac8), ah[m]);
#pragma unroll
        for (int nn = 0; nn < 4; nn++) {
#pragma unroll
            for (int m = 0; m < 2; m++) {
                mma16816(acc[m * 8 + nn * 2], ah[m], bfr[nn].x, bfr[nn].y);
                mma16816(acc[m * 8 + nn * 2 + 1], ah[m], bfr[nn].z, bfr[nn].w);
            }
        }
    }
    __syncthreads();   // all warps done reading A -> epilogue may overwrite
}

#define INIT_BIAS16(bp)                                                   \
    { _Pragma("unroll") for (int p = 0; p < 16; p++) {                    \
        int col = nh * 64 + (p & 7) * 8 + 2 * t;                          \
        float b0 = __ldg((bp) + col), b1 = __ldg((bp) + col + 1);         \
        acc[p][0] = b0; acc[p][1] = b1; acc[p][2] = b0; acc[p][3] = b1; } }

__device__ __forceinline__ void reduce_rows16(float acc[16][4], const float* w,
                                              float* red, int s, int nh,
                                              int g, int t) {
    float ra[2] = {0.f, 0.f}, rb[2] = {0.f, 0.f};
#pragma unroll
    for (int p = 0; p < 16; p++) {
        int m = p >> 3, col = nh * 64 + (p & 7) * 8 + 2 * t;
        float w0 = w ? __ldg(w + col) : 1.f;
        float w1 = w ? __ldg(w + col + 1) : 1.f;
        ra[m] += ftanh(acc[p][0]) * w0 + ftanh(acc[p][1]) * w1;
        rb[m] += ftanh(acc[p][2]) * w0 + ftanh(acc[p][3]) * w1;
    }
#pragma unroll
    for (int m = 0; m < 2; m++) {
        ra[m] += __shfl_xor_sync(~0u, ra[m], 1); ra[m] += __shfl_xor_sync(~0u, ra[m], 2);
        rb[m] += __shfl_xor_sync(~0u, rb[m], 1); rb[m] += __shfl_xor_sync(~0u, rb[m], 2);
        if (t == 0) {
            red[(s * 32 + m * 16 + g) * 2 + nh] = ra[m];
            red[(s * 32 + m * 16 + 8 + g) * 2 + nh] = rb[m];
        }
    }
}

// fragment-order (k,n) decode
__device__ __forceinline__ void fragkn(int o, int& k, int& n) {
    int q = o & 7, lane = (o >> 3) & 31, jj = (o >> 8) & 7, c = o >> 11;
    int j = jj * 2 + (q >> 2), fi = q & 3;
    k = c * 16 + (lane & 3) * 2 + (fi & 1) + ((fi & 2) ? 8 : 0);
    n = j * 8 + (lane >> 2);
}

__global__ __launch_bounds__(256) void prep_kernel(
        const float* __restrict__ We1, const float* __restrict__ We2,
        const float* __restrict__ Wx1, const float* __restrict__ Wv1,
        const float* __restrict__ Wh1, const float* __restrict__ Wh2) {
    int o = blockIdx.x * 256 + threadIdx.x;
    float v; __half* dst; int idx, k, n;
    if (o < F * F) {
        idx = o; dst = g_Wpi; fragkn(o, k, n); v = __ldg(We1 + k * F + n);
    } else if ((o -= F * F) < KE * F) {
        idx = o; dst = g_W1; fragkn(o, k, n);
        int src = (k < 128) ? (128 + k) : (129 + k);   // skip row 256 (r)
        v = __ldg(We1 + src * F + n);
    } else if ((o -= KE * F) < F * F) {
        idx = o; dst = g_W2; fragkn(o, k, n); v = __ldg(We2 + k * F + n);
    } else if ((o -= F * F) < F * F) {
        idx = o; dst = g_Wx; fragkn(o, k, n); v = __ldg(Wx1 + k * F + n);
    } else if ((o -= F * F) < F * F) {
        idx = o; dst = g_Wv; fragkn(o, k, n); v = __ldg(Wv1 + k * F + n);
    } else if ((o -= F * F) < KH * F) {
        idx = o; dst = g_Wh1; fragkn(o, k, n); v = __ldg(Wh1 + k * F + n);
    } else if ((o -= KH * F) < F * F) {
        idx = o; dst = g_Wh2; fragkn(o, k, n); v = __ldg(Wh2 + k * F + n);
    } else return;
    dst[idx] = __float2half_rn(v);
}

// ---------------- pi kernel: Pi = h[0:3125] @ We1[0:128] + be1 -------------
__global__ __launch_bounds__(256, 2) void pi_kernel(const float* __restrict__ h,
                                                    const float* __restrict__ be1) {
    extern __shared__ __align__(16) char smraw[];
    __half* Ah = (__half*)smraw;            // [128][SPI]

    int tid = threadIdx.x, lane = tid & 31, wid = tid >> 5;
    int s = wid & 3, nh = wid >> 2, g = lane >> 2, t = lane & 3;
    int i0 = blockIdx.x * 128;

    {
        int e = tid >> 1, q = tid & 1;
        int i = i0 + e; if (i >= NI) i = NI - 1;
        const float* ph = h + (size_t)i * F + q * 64;
#pragma unroll
        for (int u = 0; u < 8; u++)
            *reinterpret_cast<uint4*>(Ah + e * SPI + q * 64 + u * 8) =
                cvt8(ldg4(ph + u * 8), ldg4(ph + u * 8 + 4));
    }
    float acc[16][4];
    INIT_BIAS16(be1);
    run_layer<8, SPI, 8>(Ah, g_Wpi, acc, tid);
#pragma unroll
    for (int p = 0; p < 16; p++) {
        int m = p >> 3, col = nh * 64 + (p & 7) * 8 + 2 * t;
        int r0 = s * 32 + m * 16 + g, r1 = r0 + 8;
        if (i0 + r0 < NI)
            *reinterpret_cast<float2*>(&g_Pi[(i0 + r0) * F + col]) =
                make_float2(acc[p][0], acc[p][1]);
        if (i0 + r1 < NI)
            *reinterpret_cast<float2*>(&g_Pi[(i0 + r1) * F + col]) =
                make_float2(acc[p][2], acc[p][3]);
    }
}

// ------------- edge kernel: 64 edges/block, 128 threads, 4 blk/SM ---------
__global__ __launch_bounds__(128, 4) void edge_kernel(
        const float* __restrict__ h, const float* __restrict__ x,
        const float* __restrict__ eattr, const int* __restrict__ cols,
        const float* __restrict__ We1, const float* __restrict__ be2,
        const float* __restrict__ bx1, const float* __restrict__ Wx2,
        const float* __restrict__ bx2) {
    extern __shared__ __align__(16) char smraw[];
    __half* Ah = (__half*)smraw;            // [64][S1]
    float* red  = (float*)(Ah + 64 * S1);       // [64][2]
    float* sumd = red + 128;                    // [64]
    float* rr   = sumd + 64;                    // [64]
    int*   cs   = (int*)(rr + 64);              // [64]

    int tid = threadIdx.x, lane = tid & 31, wid = tid >> 5;
    int s = wid & 1, nh = wid >> 1, g = lane >> 2, t = lane & 3;
    int j0 = blockIdx.x * 64;

    if (tid < 64) {
        int j = j0 + tid; if (j >= NE) j = NE - 1;
        int c = __ldg(cols + j);
        cs[tid] = c;
        int i = j >> 4;
        float dx = x[i * 3 + 0] - x[c * 3 + 0];
        float dy = x[i * 3 + 1] - x[c * 3 + 1];
        float dz = x[i * 3 + 2] - x[c * 3 + 2];
        sumd[tid] = dx + dy + dz;
        rr[tid] = dx * dx + dy * dy + dz * dz;
        const float* pe = eattr + (size_t)j * 16;
        *reinterpret_cast<uint4*>(Ah + tid * S1 + 128) =
            cvt8(ldg4(pe), ldg4(pe + 4));
        *reinterpret_cast<uint4*>(Ah + tid * S1 + 136) =
            cvt8(ldg4(pe + 8), ldg4(pe + 12));
    }
    __syncthreads();
    {   // gather h_j into cols 0..127 (2 threads per row)
        int e = tid >> 1, q = tid & 1;
        const float* pj = h + (size_t)cs[e] * F + q * 64;
#pragma unroll
        for (int u = 0; u < 8; u++)
            *reinterpret_cast<uint4*>(Ah + e * S1 + q * 64 + u * 8) =
                cvt8(ldg4(pj + u * 8), ldg4(pj + u * 8 + 4));
    }
    float acc[16][4];

    // layer 1: acc = Pi + r * We1[256]  (per-row fp32 exact)
    {
        const float* Wr = We1 + 256 * F;
#pragma unroll
        for (int p = 0; p < 16; p++) {
            int m = p >> 3;
            int iPi = j0 / 16 + 2 * s + m;
            if (iPi >= NI) iPi = NI - 1;
            int col = nh * 64 + (p & 7) * 8 + 2 * t;
            int r0 = s * 32 + m * 16 + g, r1 = r0 + 8;
            float2 pv = *reinterpret_cast<const float2*>(&g_Pi[iPi * F + col]);
            float2 w = ldg2(Wr + col);
            acc[p][0] = fmaf(rr[r0], w.x, pv.x);
            acc[p][1] = fmaf(rr[r0], w.y, pv.y);
            acc[p][2] = fmaf(rr[r1], w.x, pv.x);
            acc[p][3] = fmaf(rr[r1], w.y, pv.y);
        }
    }
    run_layer<KE / 16, S1, 4>(Ah, g_W1, acc, tid);
#pragma unroll
    for (int p = 0; p < 16; p++) {   // t1 -> A
        int m = p >> 3, col = nh * 64 + (p & 7) * 8 + 2 * t;
        int r0 = s * 32 + m * 16 + g, r1 = r0 + 8;
        st_hi(Ah + r0 * S1 + col, ftanh(acc[p][0]), ftanh(acc[p][1]));
        st_hi(Ah + r1 * S1 + col, ftanh(acc[p][2]), ftanh(acc[p][3]));
    }
    // layer 2: m = tanh(t1 @ We2 + be2); sM
    INIT_BIAS16(be2);
    run_layer<8, S1, 4>(Ah, g_W2, acc, tid);
    {
        float ra[2] = {0.f, 0.f}, rb[2] = {0.f, 0.f};
#pragma unroll
        for (int p = 0; p < 16; p++) {
            int m = p >> 3, col = nh * 64 + (p & 7) * 8 + 2 * t;
            int r0 = s * 32 + m * 16 + g, r1 = r0 + 8;
            float m0 = ftanh(acc[p][0]), m1 = ftanh(acc[p][1]);
            float m2 = ftanh(acc[p][2]), m3 = ftanh(acc[p][3]);
            st_hi(Ah + r0 * S1 + col, m0, m1);
            st_hi(Ah + r1 * S1 + col, m2, m3);
            ra[m] += m0 + m1; rb[m] += m2 + m3;
        }
#pragma unroll
        for (int m = 0; m < 2; m++) {
            ra[m] += __shfl_xor_sync(~0u, ra[m], 1); ra[m] += __shfl_xor_sync(~0u, ra[m], 2);
            rb[m] += __shfl_xor_sync(~0u, rb[m], 1); rb[m] += __shfl_xor_sync(~0u, rb[m], 2);
            if (t == 0) {
                red[(s * 32 + m * 16 + g) * 2 + nh] = ra[m];
                red[(s * 32 + m * 16 + 8 + g) * 2 + nh] = rb[m];
            }
        }
    }
    __syncthreads();
    if (tid < 64) {
        int j = j0 + tid;
        if (j < NE)
            ((float*)g_sMA)[2 * j] = red[tid * 2] + red[tid * 2 + 1];
    }
    // layer 3: u = tanh(m@Wx1+bx1); phi = tanh(u.Wx2+bx2); sA
    INIT_BIAS16(bx1);
    run_layer<8, S1, 4>(Ah, g_Wx, acc, tid);
    reduce_rows16(acc, Wx2, red, s, nh, g, t);
    __syncthreads();
    if (tid < 64) {
        int j = j0 + tid;
        if (j < NE) {
            float phi = ftanh(red[tid * 2] + red[tid * 2 + 1] + __ldg(bx2));
            ((float*)g_sMA)[2 * j + 1] = phi * sumd[tid];
        }
    }
}

// ---------------- node kernel: 64 nodes/block, 128 threads, 4 blk/SM ------
__global__ __launch_bounds__(128, 4) void node_kernel(
        const float* __restrict__ h, const float* __restrict__ x,
        const float* __restrict__ vel, const int* __restrict__ cols,
        const float* __restrict__ bv1, const float* __restrict__ Wv2,
        const float* __restrict__ bv2, const float* __restrict__ Wh1,
        const float* __restrict__ bh1, const float* __restrict__ bh2,
        float* __restrict__ out_h, float* __restrict__ out_x,
        float* __restrict__ out_v) {
    extern __shared__ __align__(16) char smraw[];
    __half* Ah = (__half*)smraw;            // [64][SN]
    float* red  = (float*)(Ah + 64 * SN);       // [64][2]
    float* meds = red + 128;                    // [64]
    float* pvs  = meds + 64;                    // [64]
    float* mis  = pvs + 64;                     // [64]

    int tid = threadIdx.x, lane = tid & 31, wid = tid >> 5;
    int s = wid & 1, nh = wid >> 1, g = lane >> 2, t = lane & 3;
    int i0 = blockIdx.x * 64;

    {
        int e = tid >> 1, q = tid & 1;
        int i = i0 + e;
        int is = (i < NN) ? i : 0;
        const float* ph = h + (size_t)is * F + q * 64;
#pragma unroll
        for (int u = 0; u < 8; u++)
            *reinterpret_cast<uint4*>(Ah + e * SN + q * 64 + u * 8) =
                cvt8(ldg4(ph + u * 8), ldg4(ph + u * 8 + 4));
        float sm = 0.f, sa = 0.f;
#pragma unroll
        for (int u = 0; u < 8; u++) {
            int c = __ldg(cols + (size_t)is * 16 + q * 8 + u);
            float2 v = __ldg(&g_sMA[c]);
            sm += v.x; sa += v.y;
        }
        sm += __shfl_xor_sync(~0u, sm, 1);
        sa += __shfl_xor_sync(~0u, sa, 1);
        if (q == 0) { meds[e] = sa * (1.f / 16.f); mis[e] = sm; }
    }
    float acc[16][4];

    // phi_v = tanh(h@Wv1+bv1).Wv2 + bv2
    INIT_BIAS16(bv1);
    run_layer<8, SN, 4>(Ah, g_Wv, acc, tid);
    reduce_rows16(acc, Wv2, red, s, nh, g, t);
    __syncthreads();
    if (tid < 64) pvs[tid] = red[tid * 2] + red[tid * 2 + 1] + __ldg(bv2);

    // t2 = tanh(h @ Wh1[0:128] + m_i*Wh1[128] + bh1)
    {
        const float* W128 = Wh1 + 128 * F;
#pragma unroll
        for (int p = 0; p < 16; p++) {
            int m = p >> 3, col = nh * 64 + (p & 7) * 8 + 2 * t;
            int r0 = s * 32 + m * 16 + g, r1 = r0 + 8;
            float2 b = ldg2(bh1 + col);
            float2 w = ldg2(W128 + col);
            acc[p][0] = fmaf(mis[r0], w.x, b.x);
            acc[p][1] = fmaf(mis[r0], w.y, b.y);
            acc[p][2] = fmaf(mis[r1], w.x, b.x);
            acc[p][3] = fmaf(mis[r1], w.y, b.y);
        }
    }
    run_layer<8, SN, 4>(Ah, g_Wh1, acc, tid);
#pragma unroll
    for (int p = 0; p < 16; p++) {
        int m = p >> 3, col = nh * 64 + (p & 7) * 8 + 2 * t;
        int r0 = s * 32 + m * 16 + g, r1 = r0 + 8;
        st_hi(Ah + r0 * SN + col, ftanh(acc[p][0]), ftanh(acc[p][1]));
        st_hi(Ah + r1 * SN + col, ftanh(acc[p][2]), ftanh(acc[p][3]));
    }
    // h_new = t2 @ Wh2 + bh2
    INIT_BIAS16(bh2);
    run_layer<8, SN, 4>(Ah, g_Wh2, acc, tid);
#pragma unroll
    for (int p = 0; p < 16; p++) {
        int m = p >> 3, col = nh * 64 + (p & 7) * 8 + 2 * t;
        int r0 = s * 32 + m * 16 + g, r1 = r0 + 8;
        int ia = i0 + r0, ib = i0 + r1;
        if (ia < NN)
            *reinterpret_cast<float2*>(&out_h[(size_t)ia * F + col]) =
                make_float2(acc[p][0], acc[p][1]);
        if (ib < NN)
            *reinterpret_cast<float2*>(&out_h[(size_t)ib * F + col]) =
                make_float2(acc[p][2], acc[p][3]);
    }
    if (tid < 64) {
        int i = i0 + tid;
        if (i < NN) {
            float pv = pvs[tid], med = meds[tid];
#pragma unroll
            for (int d = 0; d < 3; d++) {
                float v = vel[i * 3 + d] * pv + med;
                out_v[i * 3 + d] = v;
                out_x[i * 3 + d] = x[i * 3 + d] + v;
            }
        }
    }
}

extern "C" void kernel_launch(void* const* d_in, const int* in_sizes, int n_in,
                              void* d_out, int out_size) {
    const float* h     = (const float*)d_in[0];
    const float* x     = (const float*)d_in[1];
    const float* vel   = (const float*)d_in[2];
    const float* eattr = (const float*)d_in[3];
    const int*   cols  = (const int*)d_in[5];
    const float* We1 = (const float*)d_in[6];
    const float* be1 = (const float*)d_in[7];
    const float* We2 = (const float*)d_in[8];
    const float* be2 = (const float*)d_in[9];
    const float* Wx1 = (const float*)d_in[10];
    const float* bx1 = (const float*)d_in[11];
    const float* Wx2 = (const float*)d_in[12];
    const float* bx2 = (const float*)d_in[13];
    const float* Wh1 = (const float*)d_in[14];
    const float* bh1 = (const float*)d_in[15];
    const float* Wh2 = (const float*)d_in[16];
    const float* bh2 = (const float*)d_in[17];
    const float* Wv1 = (const float*)d_in[18];
    const float* bv1 = (const float*)d_in[19];
    const float* Wv2 = (const float*)d_in[20];
    const float* bv2 = (const float*)d_in[21];

    float* out   = (float*)d_out;
    float* out_h = out;
    float* out_x = out + (size_t)NN * F;
    float* out_v = out_x + (size_t)NN * 3;

    int smem_pi   = 128 * SPI * 2;
    int smem_edge = 64 * S1 * 2 + (128 + 64 + 64 + 64) * 4;
    int smem_node = 64 * SN * 2 + (128 + 64 + 64 + 64) * 4;
    cudaFuncSetAttribute((const void*)pi_kernel,
                         cudaFuncAttributeMaxDynamicSharedMemorySize, smem_pi);
    cudaFuncSetAttribute((const void*)edge_kernel,
                         cudaFuncAttributeMaxDynamicSharedMemorySize, smem_edge);
    cudaFuncSetAttribute((const void*)node_kernel,
                         cudaFuncAttributeMaxDynamicSharedMemorySize, smem_node);

    int prep_elems = 5 * F * F + KE * F + KH * F;
    prep_kernel<<<(prep_elems + 255) / 256, 256>>>(We1, We2, Wx1, Wv1, Wh1, Wh2);
    pi_kernel<<<(NI + 127) / 128, 256, smem_pi>>>(h, be1);
    edge_kernel<<<(NE + 63) / 64, 128, smem_edge>>>(
        h, x, eattr, cols, We1, be2, bx1, Wx2, bx2);
    node_kernel<<<(NN + 63) / 64, 128, smem_node>>>(
        h, x, vel, cols, bv1, Wv2, bv2, Wh1, bh1, bh2, out_h, out_x, out_v);
}